// round 13
// baseline (speedup 1.0000x reference)
#include <cuda_runtime.h>

#define NK   10
#define NSEG 9
#define FF   256
#define VROWS 2
#define NCTA_B 6
#define NTAB 262144                      // fine phi-table intervals (2^18)
#define NCO  4096                        // coarse (smem) intervals
#define CSTR (NTAB / NCO)                // 64 fine per coarse
#define PHI_PTS (NTAB + 1 + 3 * NTAB)    // grid + 3 check points per interval
#define APPLY_SMEM (NCO * 16 + NSEG * 16 + 64)

// ---------------- device-global scratch (no allocations allowed) ----------------
__device__ float4 g_coef4[NSEG * FF];
__device__ float2 g_k0inv[FF];
__device__ float  g_knotsg[FF * NK];
__device__ float2 g_kx2[FF * NSEG];
__device__ int    g_uniform;
__device__ int    g_tiny;
__device__ float  g_phiV[NTAB + 1];      // exact Phi at grid points      (1 MB)
__device__ float  g_phiM[3 * NTAB];      // exact Phi at interior checks  (3 MB)
__device__ float4 g_tab4[NTAB];          // fine CR coeffs; NaN = risky   (4 MB)
__device__ unsigned char g_flagB[NTAB];  // fine risky bytes (build-time only)
__device__ float4 g_ctab[NCO];           // coarse CR coeffs; NaN = use fine (64 KB)

// ---------------- kernel 1: per-feature spline coefficients ----------------
__global__ void coeff_kernel(const float* __restrict__ W) {
    __shared__ int s_uni, s_same;
    int f = threadIdx.x;
    if (f == 0) { s_uni = 1; s_same = 1; }
    __syncthreads();

    float kx[NK], yv[NK];
#pragma unroll
    for (int j = 0; j < NK; j++) {
        kx[j] = W[f * NK + j];
        yv[j] = (j & 1) ? -1.0f : 1.0f;
        g_knotsg[f * NK + j] = kx[j];
    }
    float h[NSEG], sl[NSEG];
#pragma unroll
    for (int j = 0; j < NSEG; j++) {
        h[j]  = kx[j + 1] - kx[j];
        sl[j] = (yv[j + 1] - yv[j]) / h[j];
    }
    float cp[8], dp[8];
    {
        float dg  = 2.0f * (h[0] + h[1]);
        float inv = 1.0f / dg;
        cp[0] = h[1] * inv;
        dp[0] = 6.0f * (sl[1] - sl[0]) * inv;
#pragma unroll
        for (int i = 1; i < 8; i++) {
            float dg2 = 2.0f * (h[i] + h[i + 1]);
            float sub = h[i];
            float den = dg2 - sub * cp[i - 1];
            float inv2 = 1.0f / den;
            cp[i] = (i < 7) ? h[i + 1] * inv2 : 0.0f;
            dp[i] = (6.0f * (sl[i + 1] - sl[i]) - sub * dp[i - 1]) * inv2;
        }
    }
    float M[NK];
    M[0] = 0.0f; M[9] = 0.0f;
    M[8] = dp[7];
#pragma unroll
    for (int i = 6; i >= 0; i--)
        M[i + 1] = dp[i] - cp[i] * M[i + 2];

    float havg  = (kx[9] - kx[0]) * (1.0f / 9.0f);
    float range = fabsf(kx[9] - kx[0]) + 1e-30f;
    float dev = 0.0f, dsame = 0.0f;
#pragma unroll
    for (int j = 0; j < NK; j++) {
        dev   = fmaxf(dev,   fabsf(kx[j] - (kx[0] + (float)j * havg)));
        dsame = fmaxf(dsame, fabsf(kx[j] - W[j]));
    }
    if (!(dev   <= 1e-4f * range)) atomicAnd(&s_uni, 0);
    if (!(dsame <= 1e-6f * range)) atomicAnd(&s_same, 0);

#pragma unroll
    for (int i = 0; i < NSEG; i++) {
        float c = 0.5f * M[i];
        float d = (M[i + 1] - M[i]) / (6.0f * h[i]);
        float b = sl[i] - h[i] * (2.0f * M[i] + M[i + 1]) * (1.0f / 6.0f);
        float4 cf;
        cf.x = yv[i];
        cf.y = b * h[i];
        cf.z = c * h[i] * h[i];
        cf.w = d * h[i] * h[i] * h[i];
        g_coef4[i * FF + f] = cf;
        g_kx2[f * NSEG + i] = make_float2(kx[i], 1.0f / h[i]);
    }
    g_k0inv[f] = make_float2(kx[0], 1.0f / havg);
    __syncthreads();
    if (f == 0) {
        g_uniform = s_uni;
        g_tiny    = s_uni & s_same;
    }
}

// ---------------- spline / RK helpers ----------------
__device__ __forceinline__ float spline_horner(float w, float4 cf) {
    return fmaf(w, fmaf(w, fmaf(w, cf.w, cf.z), cf.y), cf.x);
}

template<int STRIDE>
__device__ __forceinline__ float eval_uni(float x, float nk0, float invh,
                                          const float4* __restrict__ tbl) {
    float t  = fmaf(x, invh, nk0);
    float ft = floorf(t);
    ft = fminf(fmaxf(ft, 0.0f), 8.0f);
    float w = t - ft;               // UNclamped: edge extrapolation matches reference
    int idx = (int)ft;
    return spline_horner(w, tbl[idx * STRIDE]);
}

__device__ __forceinline__ float eval_gen(float x, int f,
                                          const float4* __restrict__ tbl) {
    int s = 0;
#pragma unroll
    for (int j = 1; j < NK; j++) s += (x >= __ldg(&g_knotsg[f * NK + j])) ? 1 : 0;
    int idx = min(s, NSEG - 1);
    float2 kv = __ldg(&g_kx2[f * NSEG + idx]);
    float w = (x - kv.x) * kv.y;
    return spline_horner(w, tbl[idx * FF]);
}

template<int STRIDE>
__device__ __forceinline__ float rk_step_uni(float x0, float nk0, float invh,
                                             const float4* __restrict__ tbl) {
    const float dt  = 1.0f / 9.0f;
    const float dt3 = dt * (1.0f / 3.0f);
    const float dt8 = dt * 0.125f;
    float k1 = eval_uni<STRIDE>(x0, nk0, invh, tbl);
    float a2 = fmaf(dt3, k1, x0);
    float k2 = eval_uni<STRIDE>(a2, nk0, invh, tbl);
    float a3 = fmaf(dt, k2, fmaf(-dt3, k1, x0));
    float k3 = eval_uni<STRIDE>(a3, nk0, invh, tbl);
    float a4 = fmaf(dt, (k1 - k2) + k3, x0);
    float k4 = eval_uni<STRIDE>(a4, nk0, invh, tbl);
    return fmaf(dt8, fmaf(3.0f, k2 + k3, k1 + k4), x0);
}

__device__ __forceinline__ float rk_step_gen(float x0, int f,
                                             const float4* __restrict__ tbl) {
    const float dt  = 1.0f / 9.0f;
    const float dt3 = dt * (1.0f / 3.0f);
    const float dt8 = dt * 0.125f;
    float k1 = eval_gen(x0, f, tbl);
    float a2 = fmaf(dt3, k1, x0);
    float k2 = eval_gen(a2, f, tbl);
    float a3 = fmaf(dt, k2, fmaf(-dt3, k1, x0));
    float k3 = eval_gen(a3, f, tbl);
    float a4 = fmaf(dt, (k1 - k2) + k3, x0);
    float k4 = eval_gen(a4, f, tbl);
    return fmaf(dt8, fmaf(3.0f, k2 + k3, k1 + k4), x0);
}

__device__ __forceinline__ float phi_exact(float x, float nk0, float invh,
                                           const float4* __restrict__ t9) {
    float st = x;
#pragma unroll 1
    for (int s = 0; s < 9; s++) st = rk_step_uni<1>(st, nk0, invh, t9);
    return st;
}

// ---------------- kernel 2: exact Phi samples (grid + check points) ----------------
__global__ void phi_grid_kernel() {
    if (!g_tiny) return;
    __shared__ float4 sT9[NSEG];
    if (threadIdx.x < NSEG) sT9[threadIdx.x] = g_coef4[threadIdx.x * FF];
    __syncthreads();
    float2 ki = g_k0inv[0];
    float invh = ki.y;
    float nk0  = -ki.x * invh;
    float hstep = 9.0f / (invh * (float)NTAB);    // range / NTAB
    float lo = ki.x;

    int pid = blockIdx.x * blockDim.x + threadIdx.x;
    if (pid < NTAB + 1) {
        float x = fmaf((float)pid, hstep, lo);    // pid <= 2^18: exact in float
        g_phiV[pid] = phi_exact(x, nk0, invh, sT9);
    } else if (pid < PHI_PTS) {
        int m = pid - (NTAB + 1);
        int i = m / 3, j = m % 3;
        float off = 0.25f * (float)(j + 1);
        float x = fmaf((float)i, hstep, fmaf(off, hstep, lo));  // avoids (i+off) rounding
        g_phiM[m] = phi_exact(x, nk0, invh, sT9);
    }
}

// ---------------- kernel 3: fine CR coeffs; risky -> NaN; byte flags for tier-1 ----
__device__ __forceinline__ float4 cr_coeffs_fine(int j) {
    float vm1 = g_phiV[max(j - 1, 0)];
    float v0  = g_phiV[j];
    float v1  = g_phiV[j + 1];
    float v2  = g_phiV[min(j + 2, NTAB)];
    float4 c;
    c.x = v0;
    c.y = 0.5f * (v1 - vm1);
    c.z = vm1 - 2.5f * v0 + 2.0f * v1 - 0.5f * v2;
    c.w = -0.5f * vm1 + 1.5f * v0 - 1.5f * v1 + 0.5f * v2;
    return c;
}

__device__ __forceinline__ bool interval_risky(int j) {
    if (j < 0 || j >= NTAB) return false;
    float v0 = g_phiV[j], v1 = g_phiV[j + 1];
    if (fabsf(v1 - v0) > 0.01f) return true;       // genuine basin jump
    float4 c = cr_coeffs_fine(j);
#pragma unroll
    for (int k = 0; k < 3; k++) {
        float s = 0.25f * (float)(k + 1);
        float p = fmaf(s, fmaf(s, fmaf(s, c.w, c.z), c.y), c.x);
        if (fabsf(p - g_phiM[3 * j + k]) > 5e-5f) return true;
    }
    return false;
}

__global__ void phi_table_kernel() {
    if (!g_tiny) return;
    int i = blockIdx.x * blockDim.x + threadIdx.x;   // NTAB divisible by 256
    bool r = interval_risky(i - 1) | interval_risky(i) | interval_risky(i + 1);
    if (i < 2 || i >= NTAB - 2) r = true;            // exact at domain edges
    float4 cf = cr_coeffs_fine(i);
    if (r) {
        float qn = __int_as_float(0x7FC00000);       // NaN marker -> exact path
        cf = make_float4(qn, qn, qn, qn);
    }
    g_tab4[i] = cf;
    g_flagB[i] = r ? 1 : 0;
}

// ---------------- kernel 3b: coarse (smem-tier) CR coeffs; NaN -> use fine --------
__global__ void phi_coarse_kernel() {
    if (!g_tiny) return;
    int i = blockIdx.x * blockDim.x + threadIdx.x;   // 0..NCO-1
    float vm1 = g_phiV[max(i - 1, 0) * CSTR];
    float v0  = g_phiV[i * CSTR];
    float v1  = g_phiV[min(i + 1, NCO) * CSTR];
    float v2  = g_phiV[min(i + 2, NCO) * CSTR];
    float4 c;
    c.x = v0;
    c.y = 0.5f * (v1 - vm1);
    c.z = vm1 - 2.5f * v0 + 2.0f * v1 - 0.5f * v2;
    c.w = -0.5f * vm1 + 1.5f * v0 - 1.5f * v1 + 0.5f * v2;

    bool bad = (i < 2) || (i >= NCO - 2);
    // any risky fine interval inside -> defer to fine tier
    for (int b = 0; b < CSTR && !bad; b++)
        bad = (g_flagB[i * CSTR + b] != 0);
    // coarse interpolant must match exact Phi at all interior fine gridpoints
    for (int k = 1; k < CSTR && !bad; k++) {
        float s = (float)k * (1.0f / (float)CSTR);
        float p = fmaf(s, fmaf(s, fmaf(s, c.w, c.z), c.y), c.x);
        bad = fabsf(p - g_phiV[i * CSTR + k]) > 5e-5f;
    }
    if (bad) {
        float qn = __int_as_float(0x7FC00000);
        c = make_float4(qn, qn, qn, qn);
    }
    g_ctab[i] = c;
}

// ---------------- kernel 4: 3-tier apply: smem -> L2 fine -> exact RK -------------
extern __shared__ unsigned char s_dyn[];

__device__ __forceinline__ float phi_tiered(float x, float lo, float invRange,
                                            float nk0, float invh,
                                            const float4* __restrict__ sC,
                                            const float4* __restrict__ sT9) {
    float u = fminf(fmaxf((x - lo) * invRange, 0.0f), 1.0f);
    // tier 1: coarse smem table
    float fic = fminf(floorf(u * (float)NCO), (float)(NCO - 1));
    float sc  = fmaf(u, (float)NCO, -fic);
    float4 cc = sC[(int)fic];
    float r = fmaf(sc, fmaf(sc, fmaf(sc, cc.w, cc.z), cc.y), cc.x);
    if (!(r == r)) {
        // tier 2: fine table in L2
        float fif = fminf(floorf(u * (float)NTAB), (float)(NTAB - 1));
        float sf  = fmaf(u, (float)NTAB, -fif);
        float4 cf = __ldcg(&g_tab4[(int)fif]);
        r = fmaf(sf, fmaf(sf, fmaf(sf, cf.w, cf.z), cf.y), cf.x);
        // tier 3: exact RK (NaN test MUST precede the clamp)
        if (!(r == r)) r = phi_exact(x, nk0, invh, sT9);
    }
    return fminf(fmaxf(r, 0.0f), 1.0f);
}

__global__ void __launch_bounds__(256)
phi_apply_kernel(const float* __restrict__ X, float* __restrict__ O, int n) {
    if (!g_tiny) return;
    float4* sC  = (float4*)s_dyn;                       // 64 KB coarse table
    float4* sT9 = (float4*)(s_dyn + NCO * 16);          // 144 B exact-path table

    int tid = threadIdx.x;
    for (int i = tid; i < NCO; i += 256) sC[i] = g_ctab[i];
    if (tid < NSEG) sT9[tid] = g_coef4[tid * FF];

    float2 ki = g_k0inv[0];
    float invh = ki.y;
    float nk0  = -ki.x * invh;
    float invRange = invh * (1.0f / 9.0f);              // 1/range
    float lo = ki.x;
    __syncthreads();

    int n4 = n >> 2;
    const float4* X4 = (const float4*)X;
    float4* O4 = (float4*)O;
    int stride = gridDim.x * blockDim.x;

    int i = blockIdx.x * blockDim.x + tid;
    // 2x unrolled main loop: two outstanding stream loads (MLP at low occupancy)
    for (; i + stride < n4; i += 2 * stride) {
        float4 va = __ldcs(&X4[i]);
        float4 vb = __ldcs(&X4[i + stride]);
        float4 ra, rb;
        ra.x = phi_tiered(va.x, lo, invRange, nk0, invh, sC, sT9);
        ra.y = phi_tiered(va.y, lo, invRange, nk0, invh, sC, sT9);
        ra.z = phi_tiered(va.z, lo, invRange, nk0, invh, sC, sT9);
        ra.w = phi_tiered(va.w, lo, invRange, nk0, invh, sC, sT9);
        rb.x = phi_tiered(vb.x, lo, invRange, nk0, invh, sC, sT9);
        rb.y = phi_tiered(vb.y, lo, invRange, nk0, invh, sC, sT9);
        rb.z = phi_tiered(vb.z, lo, invRange, nk0, invh, sC, sT9);
        rb.w = phi_tiered(vb.w, lo, invRange, nk0, invh, sC, sT9);
        __stcs(&O4[i], ra);
        __stcs(&O4[i + stride], rb);
    }
    for (; i < n4; i += stride) {
        float4 v = __ldcs(&X4[i]);
        float4 r;
        r.x = phi_tiered(v.x, lo, invRange, nk0, invh, sC, sT9);
        r.y = phi_tiered(v.y, lo, invRange, nk0, invh, sC, sT9);
        r.z = phi_tiered(v.z, lo, invRange, nk0, invh, sC, sT9);
        r.w = phi_tiered(v.w, lo, invRange, nk0, invh, sC, sT9);
        __stcs(&O4[i], r);
    }
    for (int j = n4 * 4 + blockIdx.x * blockDim.x + tid; j < n; j += stride)
        O[j] = phi_tiered(X[j], lo, invRange, nk0, invh, sC, sT9);
}

// ---------------- kernel 5: proven R3 fallback (non-identical/non-uniform knots) ----
__global__ void __launch_bounds__(FF, NCTA_B)
ode_kernel_full(const float* __restrict__ X, float* __restrict__ O, int rows) {
    if (g_tiny) return;
    __shared__ float4 sCoef[NSEG * FF];   // 36 KB
    int f = threadIdx.x;
    for (int i = threadIdx.x; i < NSEG * FF; i += FF) sCoef[i] = g_coef4[i];

    bool uni  = (g_uniform != 0);
    float2 ki = g_k0inv[f];
    float invh = ki.y;
    float nk0  = -ki.x * invh;
    __syncthreads();
    const float4* tbl = sCoef + f;

    for (int row0 = blockIdx.x * VROWS; row0 < rows; row0 += gridDim.x * VROWS) {
        float st[VROWS];
#pragma unroll
        for (int v = 0; v < VROWS; v++) {
            int r = row0 + v;
            st[v] = (r < rows) ? X[(size_t)r * FF + f] : 0.0f;
        }
#pragma unroll 1
        for (int s = 0; s < 9; s++) {
#pragma unroll
            for (int v = 0; v < VROWS; v++)
                st[v] = uni ? rk_step_uni<FF>(st[v], nk0, invh, tbl)
                            : rk_step_gen(st[v], f, tbl);
        }
#pragma unroll
        for (int v = 0; v < VROWS; v++) {
            int r = row0 + v;
            if (r < rows) O[(size_t)r * FF + f] = fminf(fmaxf(st[v], 0.0f), 1.0f);
        }
    }
}

// ---------------- harness entry ----------------
extern "C" void kernel_launch(void* const* d_in, const int* in_sizes, int n_in,
                              void* d_out, int out_size) {
    const float* x = (const float*)d_in[0];   // [B, 256] fp32
    const float* w = (const float*)d_in[1];   // [256, 10] fp32
    (void)n_in; (void)out_size;
    int n = in_sizes[0];
    int rows = n / FF;

    cudaFuncSetAttribute(phi_apply_kernel,
                         cudaFuncAttributeMaxDynamicSharedMemorySize, APPLY_SMEM);

    coeff_kernel<<<1, FF>>>(w);
    phi_grid_kernel<<<(PHI_PTS + 255) / 256, 256>>>();
    phi_table_kernel<<<NTAB / 256, 256>>>();
    phi_coarse_kernel<<<NCO / 256, 256>>>();

    int nbF = 148 * 3;                        // 3 CTAs/SM (64KB smem each)
    int n4 = n >> 2;
    int maxF = (n4 + 255) / 256; if (nbF > maxF && maxF > 0) nbF = maxF;
    phi_apply_kernel<<<nbF, 256, APPLY_SMEM>>>(x, (float*)d_out, n);

    int nbB = 148 * NCTA_B;
    int maxb = (rows + VROWS - 1) / VROWS; if (nbB > maxb) nbB = maxb;
    ode_kernel_full<<<nbB, FF>>>(x, (float*)d_out, rows);
}

// round 16
// speedup vs baseline: 1.3140x; 1.3140x over previous
#include <cuda_runtime.h>

#define NK   10
#define NSEG 9
#define FF   256
#define VROWS 2
#define NCTA_B 6
#define NTAB 262144                      // phi-table intervals (2^18)
#define NPV  (2 * NTAB + 1)              // dense grid: table points + midpoints
#define PHI_PTS NPV

// ---------------- device-global scratch (no allocations allowed) ----------------
__device__ float4 g_coef4[NSEG * FF];
__device__ float2 g_k0inv[FF];
__device__ float  g_knotsg[FF * NK];
__device__ float2 g_kx2[FF * NSEG];
__device__ int    g_uniform;
__device__ int    g_tiny;
__device__ float  g_phiV[NPV];           // exact Phi on 2x-dense grid (2 MB)
__device__ float4 g_tab4[NTAB];          // Catmull-Rom coeffs; NaN = risky (4 MB)

// ---------------- kernel 1: per-feature spline coefficients ----------------
__global__ void coeff_kernel(const float* __restrict__ W) {
    __shared__ int s_uni, s_same;
    int f = threadIdx.x;
    if (f == 0) { s_uni = 1; s_same = 1; }
    __syncthreads();

    float kx[NK], yv[NK];
#pragma unroll
    for (int j = 0; j < NK; j++) {
        kx[j] = W[f * NK + j];
        yv[j] = (j & 1) ? -1.0f : 1.0f;
        g_knotsg[f * NK + j] = kx[j];
    }
    float h[NSEG], sl[NSEG];
#pragma unroll
    for (int j = 0; j < NSEG; j++) {
        h[j]  = kx[j + 1] - kx[j];
        sl[j] = (yv[j + 1] - yv[j]) / h[j];
    }
    float cp[8], dp[8];
    {
        float dg  = 2.0f * (h[0] + h[1]);
        float inv = 1.0f / dg;
        cp[0] = h[1] * inv;
        dp[0] = 6.0f * (sl[1] - sl[0]) * inv;
#pragma unroll
        for (int i = 1; i < 8; i++) {
            float dg2 = 2.0f * (h[i] + h[i + 1]);
            float sub = h[i];
            float den = dg2 - sub * cp[i - 1];
            float inv2 = 1.0f / den;
            cp[i] = (i < 7) ? h[i + 1] * inv2 : 0.0f;
            dp[i] = (6.0f * (sl[i + 1] - sl[i]) - sub * dp[i - 1]) * inv2;
        }
    }
    float M[NK];
    M[0] = 0.0f; M[9] = 0.0f;
    M[8] = dp[7];
#pragma unroll
    for (int i = 6; i >= 0; i--)
        M[i + 1] = dp[i] - cp[i] * M[i + 2];

    float havg  = (kx[9] - kx[0]) * (1.0f / 9.0f);
    float range = fabsf(kx[9] - kx[0]) + 1e-30f;
    float dev = 0.0f, dsame = 0.0f;
#pragma unroll
    for (int j = 0; j < NK; j++) {
        dev   = fmaxf(dev,   fabsf(kx[j] - (kx[0] + (float)j * havg)));
        dsame = fmaxf(dsame, fabsf(kx[j] - W[j]));
    }
    if (!(dev   <= 1e-4f * range)) atomicAnd(&s_uni, 0);
    if (!(dsame <= 1e-6f * range)) atomicAnd(&s_same, 0);

#pragma unroll
    for (int i = 0; i < NSEG; i++) {
        float c = 0.5f * M[i];
        float d = (M[i + 1] - M[i]) / (6.0f * h[i]);
        float b = sl[i] - h[i] * (2.0f * M[i] + M[i + 1]) * (1.0f / 6.0f);
        float4 cf;
        cf.x = yv[i];
        cf.y = b * h[i];
        cf.z = c * h[i] * h[i];
        cf.w = d * h[i] * h[i] * h[i];
        g_coef4[i * FF + f] = cf;
        g_kx2[f * NSEG + i] = make_float2(kx[i], 1.0f / h[i]);
    }
    g_k0inv[f] = make_float2(kx[0], 1.0f / havg);
    __syncthreads();
    if (f == 0) {
        g_uniform = s_uni;
        g_tiny    = s_uni & s_same;
    }
}

// ---------------- spline / RK helpers ----------------
__device__ __forceinline__ float spline_horner(float w, float4 cf) {
    return fmaf(w, fmaf(w, fmaf(w, cf.w, cf.z), cf.y), cf.x);
}

template<int STRIDE>
__device__ __forceinline__ float eval_uni(float x, float nk0, float invh,
                                          const float4* __restrict__ tbl) {
    float t  = fmaf(x, invh, nk0);
    float ft = floorf(t);
    ft = fminf(fmaxf(ft, 0.0f), 8.0f);
    float w = t - ft;               // UNclamped: edge extrapolation matches reference
    int idx = (int)ft;
    return spline_horner(w, tbl[idx * STRIDE]);
}

__device__ __forceinline__ float eval_gen(float x, int f,
                                          const float4* __restrict__ tbl) {
    int s = 0;
#pragma unroll
    for (int j = 1; j < NK; j++) s += (x >= __ldg(&g_knotsg[f * NK + j])) ? 1 : 0;
    int idx = min(s, NSEG - 1);
    float2 kv = __ldg(&g_kx2[f * NSEG + idx]);
    float w = (x - kv.x) * kv.y;
    return spline_horner(w, tbl[idx * FF]);
}

template<int STRIDE>
__device__ __forceinline__ float rk_step_uni(float x0, float nk0, float invh,
                                             const float4* __restrict__ tbl) {
    const float dt  = 1.0f / 9.0f;
    const float dt3 = dt * (1.0f / 3.0f);
    const float dt8 = dt * 0.125f;
    float k1 = eval_uni<STRIDE>(x0, nk0, invh, tbl);
    float a2 = fmaf(dt3, k1, x0);
    float k2 = eval_uni<STRIDE>(a2, nk0, invh, tbl);
    float a3 = fmaf(dt, k2, fmaf(-dt3, k1, x0));
    float k3 = eval_uni<STRIDE>(a3, nk0, invh, tbl);
    float a4 = fmaf(dt, (k1 - k2) + k3, x0);
    float k4 = eval_uni<STRIDE>(a4, nk0, invh, tbl);
    return fmaf(dt8, fmaf(3.0f, k2 + k3, k1 + k4), x0);
}

__device__ __forceinline__ float rk_step_gen(float x0, int f,
                                             const float4* __restrict__ tbl) {
    const float dt  = 1.0f / 9.0f;
    const float dt3 = dt * (1.0f / 3.0f);
    const float dt8 = dt * 0.125f;
    float k1 = eval_gen(x0, f, tbl);
    float a2 = fmaf(dt3, k1, x0);
    float k2 = eval_gen(a2, f, tbl);
    float a3 = fmaf(dt, k2, fmaf(-dt3, k1, x0));
    float k3 = eval_gen(a3, f, tbl);
    float a4 = fmaf(dt, (k1 - k2) + k3, x0);
    float k4 = eval_gen(a4, f, tbl);
    return fmaf(dt8, fmaf(3.0f, k2 + k3, k1 + k4), x0);
}

__device__ __forceinline__ float phi_exact(float x, float nk0, float invh,
                                           const float4* __restrict__ t9) {
    float st = x;
#pragma unroll 1
    for (int s = 0; s < 9; s++) st = rk_step_uni<1>(st, nk0, invh, t9);
    return st;
}

// ---------------- kernel 2: exact Phi on the 2x-dense grid ----------------
__global__ void phi_grid_kernel() {
    if (!g_tiny) return;
    __shared__ float4 sT9[NSEG];
    if (threadIdx.x < NSEG) sT9[threadIdx.x] = g_coef4[threadIdx.x * FF];
    __syncthreads();
    float2 ki = g_k0inv[0];
    float invh = ki.y;
    float nk0  = -ki.x * invh;
    float hstep2 = 9.0f / (invh * (float)(2 * NTAB));   // range / (2*NTAB)
    float lo = ki.x;

    int pid = blockIdx.x * blockDim.x + threadIdx.x;
    if (pid < NPV) {
        float x = fmaf((float)pid, hstep2, lo);          // pid <= 2^19: exact in float
        g_phiV[pid] = phi_exact(x, nk0, invh, sT9);
    }
}

// ---------------- kernel 3: Catmull-Rom coeffs (even pts) + midpoint risky check --
__device__ __forceinline__ float4 cr_coeffs(int j) {
    // table gridpoints are EVEN dense-grid indices
    float vm1 = g_phiV[2 * max(j - 1, 0)];
    float v0  = g_phiV[2 * j];
    float v1  = g_phiV[2 * min(j + 1, NTAB)];
    float v2  = g_phiV[2 * min(j + 2, NTAB)];
    float4 c;
    c.x = v0;
    c.y = 0.5f * (v1 - vm1);
    c.z = vm1 - 2.5f * v0 + 2.0f * v1 - 0.5f * v2;
    c.w = -0.5f * vm1 + 1.5f * v0 - 1.5f * v1 + 0.5f * v2;
    return c;
}

__device__ __forceinline__ bool interval_risky(int j) {
    if (j < 0 || j >= NTAB) return false;
    float v0 = g_phiV[2 * j], v1 = g_phiV[2 * j + 2];
    if (fabsf(v1 - v0) > 0.01f) return true;             // genuine basin jump
    float4 c = cr_coeffs(j);
    // CR at the midpoint (s = 0.5) vs exact dense-grid sample
    float p = c.x + 0.5f * c.y + 0.25f * c.z + 0.125f * c.w;
    return fabsf(p - g_phiV[2 * j + 1]) > 5e-5f;
}

__global__ void phi_table_kernel() {
    if (!g_tiny) return;
    int i = blockIdx.x * blockDim.x + threadIdx.x;       // NTAB divisible by 256
    bool r = interval_risky(i - 1) | interval_risky(i) | interval_risky(i + 1);
    if (i < 2 || i >= NTAB - 2) r = true;                // exact at domain edges
    float4 cf = cr_coeffs(i);
    if (r) {
        float qn = __int_as_float(0x7FC00000);           // NaN marker -> exact path
        cf = make_float4(qn, qn, qn, qn);
    }
    g_tab4[i] = cf;
}

// ---------------- kernel 4: fast path — single L2 gather per element --------------
__global__ void __launch_bounds__(256)
phi_apply_kernel(const float* __restrict__ X, float* __restrict__ O, int n) {
    if (!g_tiny) return;
    __shared__ float4 sT9[NSEG];                  // 144 B: exact-path spline table
    if (threadIdx.x < NSEG) sT9[threadIdx.x] = g_coef4[threadIdx.x * FF];

    float2 ki = g_k0inv[0];
    float invh = ki.y;
    float nk0  = -ki.x * invh;
    float invRange = invh * (1.0f / 9.0f);        // 1/range
    float lo = ki.x;
    __syncthreads();

    int n4 = n >> 2;
    const float4* X4 = (const float4*)X;
    float4* O4 = (float4*)O;
    int stride = gridDim.x * blockDim.x;

    for (int i = blockIdx.x * blockDim.x + threadIdx.x; i < n4; i += stride) {
        float4 v = __ldcs(&X4[i]);                // streaming: don't thrash caches
        float xs[4] = {v.x, v.y, v.z, v.w};
        float rs[4];
#pragma unroll
        for (int c = 0; c < 4; c++) {
            float x = xs[c];
            float u = (x - lo) * invRange;                 // in [0,1]
            u = fminf(fmaxf(u, 0.0f), 1.0f);
            float fidx = floorf(u * (float)NTAB);
            fidx = fminf(fidx, (float)(NTAB - 1));
            int idx = (int)fidx;
            // precision-safe fraction: single rounding via fmaf (NOT t - floor(t))
            float s = fmaf(u, (float)NTAB, -fidx);
            float4 cf = __ldcg(&g_tab4[idx]);              // L2-only gather (sole load)
            float r = fmaf(s, fmaf(s, fmaf(s, cf.w, cf.z), cf.y), cf.x);
            // NaN marker test MUST precede the clamp (fmaxf would swallow NaN)
            if (!(r == r)) r = phi_exact(x, nk0, invh, sT9);
            rs[c] = fminf(fmaxf(r, 0.0f), 1.0f);
        }
        __stcs(&O4[i], make_float4(rs[0], rs[1], rs[2], rs[3]));
    }
    for (int i = n4 * 4 + blockIdx.x * blockDim.x + threadIdx.x; i < n; i += stride) {
        float x = X[i];
        float u = fminf(fmaxf((x - lo) * invRange, 0.0f), 1.0f);
        float fidx = fminf(floorf(u * (float)NTAB), (float)(NTAB - 1));
        int idx = (int)fidx;
        float s = fmaf(u, (float)NTAB, -fidx);
        float4 cf = __ldcg(&g_tab4[idx]);
        float r = fmaf(s, fmaf(s, fmaf(s, cf.w, cf.z), cf.y), cf.x);
        if (!(r == r)) r = phi_exact(x, nk0, invh, sT9);
        O[i] = fminf(fmaxf(r, 0.0f), 1.0f);
    }
}

// ---------------- kernel 5: proven R3 fallback (non-identical/non-uniform knots) ----
__global__ void __launch_bounds__(FF, NCTA_B)
ode_kernel_full(const float* __restrict__ X, float* __restrict__ O, int rows) {
    if (g_tiny) return;
    __shared__ float4 sCoef[NSEG * FF];   // 36 KB
    int f = threadIdx.x;
    for (int i = threadIdx.x; i < NSEG * FF; i += FF) sCoef[i] = g_coef4[i];

    bool uni  = (g_uniform != 0);
    float2 ki = g_k0inv[f];
    float invh = ki.y;
    float nk0  = -ki.x * invh;
    __syncthreads();
    const float4* tbl = sCoef + f;

    for (int row0 = blockIdx.x * VROWS; row0 < rows; row0 += gridDim.x * VROWS) {
        float st[VROWS];
#pragma unroll
        for (int v = 0; v < VROWS; v++) {
            int r = row0 + v;
            st[v] = (r < rows) ? X[(size_t)r * FF + f] : 0.0f;
        }
#pragma unroll 1
        for (int s = 0; s < 9; s++) {
#pragma unroll
            for (int v = 0; v < VROWS; v++)
                st[v] = uni ? rk_step_uni<FF>(st[v], nk0, invh, tbl)
                            : rk_step_gen(st[v], f, tbl);
        }
#pragma unroll
        for (int v = 0; v < VROWS; v++) {
            int r = row0 + v;
            if (r < rows) O[(size_t)r * FF + f] = fminf(fmaxf(st[v], 0.0f), 1.0f);
        }
    }
}

// ---------------- harness entry ----------------
extern "C" void kernel_launch(void* const* d_in, const int* in_sizes, int n_in,
                              void* d_out, int out_size) {
    const float* x = (const float*)d_in[0];   // [B, 256] fp32
    const float* w = (const float*)d_in[1];   // [256, 10] fp32
    (void)n_in; (void)out_size;
    int n = in_sizes[0];
    int rows = n / FF;

    coeff_kernel<<<1, FF>>>(w);
    phi_grid_kernel<<<(PHI_PTS + 255) / 256, 256>>>();
    phi_table_kernel<<<NTAB / 256, 256>>>();

    int nbF = 148 * 8;
    int n4 = n >> 2;
    int maxF = (n4 + 255) / 256; if (nbF > maxF && maxF > 0) nbF = maxF;
    phi_apply_kernel<<<nbF, 256>>>(x, (float*)d_out, n);

    int nbB = 148 * NCTA_B;
    int maxb = (rows + VROWS - 1) / VROWS; if (nbB > maxb) nbB = maxb;
    ode_kernel_full<<<nbB, FF>>>(x, (float*)d_out, rows);
}